// round 3
// baseline (speedup 1.0000x reference)
#include <cuda_runtime.h>
#include <cuda_bf16.h>

// VQ codebook quantization, FFMA2 (f32x2) version — full-D fix.
//   s[n,k] = z[n]·e[k] - 0.5*||e[k]||^2 ; idx[n] = argmax_k s ; out = e[idx]
// N = 65536, D = 64, K = 1024.
// Output: [N*D floats quantized][N floats indices].
//
// Each thread owns one z row in registers (32 natural f32x2 pairs = 64 floats).
// E chunk staged in smem in natural [code][d] layout (coalesced, conflict-free,
// no transpose); all lanes read the same e address -> broadcast LDS.
// Dot products via fma.rn.f32x2 (2 FMA/issue; only reachable from PTX),
// doubling the fp32 roofline vs scalar FFMA.

#define DDIM 64
#define TKC 64          // codes per smem chunk
#define KMAX 4096

__device__ float g_cnorm[KMAX];

__global__ void cnorm_kernel(const float* __restrict__ emb, int K) {
    int k = blockIdx.x * blockDim.x + threadIdx.x;
    if (k < K) {
        const float4* e4 = reinterpret_cast<const float4*>(emb + (size_t)k * DDIM);
        float s = 0.f;
#pragma unroll
        for (int i = 0; i < DDIM / 4; i++) {
            float4 v = e4[i];
            s += v.x * v.x + v.y * v.y + v.z * v.z + v.w * v.w;
        }
        g_cnorm[k] = 0.5f * s;
    }
}

#define FMA2(acc, a, b) \
    asm("fma.rn.f32x2 %0, %1, %2, %0;" : "+l"(acc) : "l"(a), "l"(b))

__device__ __forceinline__ float pair_hsum(unsigned long long a,
                                           unsigned long long b) {
    unsigned long long t;
    asm("add.rn.f32x2 %0, %1, %2;" : "=l"(t) : "l"(a), "l"(b));
    float lo, hi;
    asm("mov.b64 {%0, %1}, %2;" : "=f"(lo), "=f"(hi) : "l"(t));
    return lo + hi;
}

__global__ __launch_bounds__(64, 8)
void vq_kernel(const float* __restrict__ z, const float* __restrict__ emb,
               float* __restrict__ out, int N, int K, int write_idx) {
    __shared__ float es[TKC * DDIM];   // 16 KB, natural [code][d]
    __shared__ float cns[TKC];

    const int tid = threadIdx.x;
    const int row = blockIdx.x * 64 + tid;
    const bool active = row < N;

    // full z row in registers: 32 f32x2 pairs = 64 floats = 256 bytes
    unsigned long long zp[32];
    if (active) {
        const ulonglong2* zr =
            reinterpret_cast<const ulonglong2*>(z + (size_t)row * DDIM);
#pragma unroll
        for (int i = 0; i < 16; i++) {
            ulonglong2 v = zr[i];
            zp[2 * i] = v.x;
            zp[2 * i + 1] = v.y;
        }
    } else {
#pragma unroll
        for (int i = 0; i < 32; i++) zp[i] = 0ull;
    }

    float best = -3.402823466e38f;
    int bidx = 0;

    for (int kc = 0; kc < K; kc += TKC) {
        __syncthreads();
        // stage chunk: 64 codes x 64 floats = 1024 float4; 16 per thread
        {
            const float4* src =
                reinterpret_cast<const float4*>(emb + (size_t)kc * DDIM);
            float4* dst = reinterpret_cast<float4*>(es);
#pragma unroll
            for (int t = 0; t < (TKC * DDIM / 4) / 64; t++)
                dst[tid + t * 64] = src[tid + t * 64];
            if (tid < TKC) cns[tid] = g_cnorm[kc + tid];
        }
        __syncthreads();

        // 2 codes per iteration; all lanes share addresses -> broadcast LDS
#pragma unroll 2
        for (int c = 0; c < TKC; c += 2) {
            const ulonglong2* e0 =
                reinterpret_cast<const ulonglong2*>(es + c * DDIM);
            const ulonglong2* e1 =
                reinterpret_cast<const ulonglong2*>(es + (c + 1) * DDIM);
            unsigned long long a0 = 0ull, a1 = 0ull;  // code c, 2 chains
            unsigned long long b0 = 0ull, b1 = 0ull;  // code c+1, 2 chains
#pragma unroll
            for (int i = 0; i < 16; i++) {            // 16 x 16B = full 256B row
                ulonglong2 ea = e0[i];
                ulonglong2 eb = e1[i];
                FMA2(a0, zp[2 * i], ea.x);
                FMA2(a1, zp[2 * i + 1], ea.y);
                FMA2(b0, zp[2 * i], eb.x);
                FMA2(b1, zp[2 * i + 1], eb.y);
            }
            float s0 = pair_hsum(a0, a1) - cns[c];
            float s1 = pair_hsum(b0, b1) - cns[c + 1];
            // codes ascend; strict > keeps first occurrence (argmin tiebreak)
            if (s0 > best) { best = s0; bidx = kc + c; }
            if (s1 > best) { best = s1; bidx = kc + c + 1; }
        }
    }

    if (active) {
        if (write_idx) out[(size_t)N * DDIM + row] = (float)bidx;
        const float4* e =
            reinterpret_cast<const float4*>(emb + (size_t)bidx * DDIM);
        float4* o = reinterpret_cast<float4*>(out + (size_t)row * DDIM);
#pragma unroll
        for (int i = 0; i < DDIM / 4; i++) o[i] = e[i];
    }
}

extern "C" void kernel_launch(void* const* d_in, const int* in_sizes, int n_in,
                              void* d_out, int out_size) {
    const float* z = (const float*)d_in[0];
    const float* emb = (const float*)d_in[1];
    if (n_in >= 2 && in_sizes[1] > in_sizes[0]) {
        const float* t = z; z = emb; emb = t;
    }
    int zsize = in_sizes[0], esize = in_sizes[1];
    if (esize > zsize) { int t = zsize; zsize = esize; esize = t; }

    int N = zsize / DDIM;   // 65536
    int K = esize / DDIM;   // 1024
    float* out = (float*)d_out;
    int write_idx = (out_size >= N * DDIM + N) ? 1 : 0;

    cnorm_kernel<<<(K + 255) / 256, 256>>>(emb, K);
    vq_kernel<<<(N + 63) / 64, 64>>>(z, emb, out, N, K, write_idx);
}

// round 5
// speedup vs baseline: 1.1730x; 1.1730x over previous
#include <cuda_runtime.h>
#include <cuda_bf16.h>

// VQ codebook quantization — FFMA2 + 8x4 register tiling (alignment fix).
//   s[n,k] = z[n]·e[k] - 0.5*||e[k]||^2 ; idx[n] = argmax_k s ; out = e[idx]
// N=65536, D=64, K=1024. Output: [N*D quantized][N indices-as-float].
//
// Tile: 128 rows x 64-code chunks, 256 threads, per-thread 8 rows x 4 codes.
// z in smem natural [row][d]; mainloop z loads are broadcast LDS.64.
// e in smem with pitch-33(f32x2) padded rows + code interleaving (tx+16j) so
// e LDS.64 bank-pair = (tx*33+kk) mod 16 is a permutation -> conflict-free.
// e staged with float2 stores (pitch 264 B is 8B- but not 16B-aligned).
// FMAs via fma.rn.f32x2 (2 FMA/issue): 12 LDS per 32 FFMA2 per kk.

#define DDIM 64
#define TM 128
#define TKC 64
#define EPITCH 33     // f32x2 per padded e row (odd => conflict-free reads)
#define KMAX 4096

__device__ float g_cnorm[KMAX];

__global__ void cnorm_kernel(const float* __restrict__ emb, int K) {
    int k = blockIdx.x * blockDim.x + threadIdx.x;
    if (k < K) {
        const float4* e4 = reinterpret_cast<const float4*>(emb + (size_t)k * DDIM);
        float s = 0.f;
#pragma unroll
        for (int i = 0; i < DDIM / 4; i++) {
            float4 v = e4[i];
            s += v.x * v.x + v.y * v.y + v.z * v.z + v.w * v.w;
        }
        g_cnorm[k] = 0.5f * s;
    }
}

#define FMA2(acc, a, b) \
    asm("fma.rn.f32x2 %0, %1, %2, %0;" : "+l"(acc) : "l"(a), "l"(b))

__global__ __launch_bounds__(256, 2)
void vq_kernel(const float* __restrict__ z, const float* __restrict__ emb,
               float* __restrict__ out, int N, int K, int write_idx) {
    extern __shared__ float smem[];
    float* zs = smem;                              // TM*DDIM = 32 KB
    float* es = smem + TM * DDIM;                  // TKC*EPITCH*2 floats
    float* cns = es + TKC * EPITCH * 2;            // TKC
    int* finalIdx = (int*)(cns + TKC);             // TM

    const int tid = threadIdx.x;
    const int tx = tid & 15;       // code groups: codes tx + 16*j
    const int ty = tid >> 4;       // row group: rows ty*8 .. ty*8+7
    const int rowBase = blockIdx.x * TM;

    // stage z tile, natural [row][d] (coalesced LDG.128 / STS.128)
#pragma unroll
    for (int t = 0; t < (TM * DDIM / 4) / 256; t++) {   // 8 iters
        int idx = tid + t * 256;
        int row = idx >> 4;
        int c4 = idx & 15;
        reinterpret_cast<float4*>(zs)[row * 16 + c4] =
            reinterpret_cast<const float4*>(z + (size_t)(rowBase + row) * DDIM)[c4];
    }

    float best[8];
    int bidx[8];
#pragma unroll
    for (int i = 0; i < 8; i++) { best[i] = -3.402823466e38f; bidx[i] = 0; }

    const unsigned long long* zs2 =
        reinterpret_cast<const unsigned long long*>(zs);
    const unsigned long long* es2 =
        reinterpret_cast<const unsigned long long*>(es);

    for (int kc = 0; kc < K; kc += TKC) {
        __syncthreads();
        // stage e chunk into padded rows with float2 stores (8B-aligned).
        // 64 codes x 32 f32x2 = 2048 float2; 8 per thread.
        {
            const float2* src = reinterpret_cast<const float2*>(
                emb + (size_t)kc * DDIM);
            float2* dst = reinterpret_cast<float2*>(es);
#pragma unroll
            for (int t = 0; t < (TKC * DDIM / 2) / 256; t++) {  // 8 iters
                int idx = tid + t * 256;
                int code = idx >> 5;          // 32 f32x2 per code row
                int c2 = idx & 31;
                dst[code * EPITCH + c2] = src[code * 32 + c2];
            }
        }
        if (tid < TKC) cns[tid] = g_cnorm[kc + tid];
        __syncthreads();

        unsigned long long acc[8][4];
#pragma unroll
        for (int i = 0; i < 8; i++)
#pragma unroll
            for (int j = 0; j < 4; j++) acc[i][j] = 0ull;

#pragma unroll 4
        for (int kk = 0; kk < DDIM / 2; kk++) {
            unsigned long long zz[8];
#pragma unroll
            for (int i = 0; i < 8; i++)
                zz[i] = zs2[(ty * 8 + i) * (DDIM / 2) + kk];  // broadcast
            unsigned long long ee[4];
#pragma unroll
            for (int j = 0; j < 4; j++)
                ee[j] = es2[(tx + 16 * j) * EPITCH + kk];     // conflict-free
#pragma unroll
            for (int i = 0; i < 8; i++)
#pragma unroll
                for (int j = 0; j < 4; j++)
                    FMA2(acc[i][j], zz[i], ee[j]);
        }

        // fold into running per-row argmax; code order ascends with j & kc
#pragma unroll
        for (int j = 0; j < 4; j++) {
            int code = kc + tx + 16 * j;
            float cn = cns[tx + 16 * j];
#pragma unroll
            for (int i = 0; i < 8; i++) {
                float lo, hi;
                asm("mov.b64 {%0, %1}, %2;" : "=f"(lo), "=f"(hi) : "l"(acc[i][j]));
                float s = (lo + hi) - cn;
                if (s > best[i]) { best[i] = s; bidx[i] = code; }
            }
        }
    }

    __syncthreads();
    // cross-tx reduction (explicit index tie-break: tx-interleaved codes)
    float* rval = es;                       // [TM][16]
    int* ridx = (int*)(es + TM * 16);       // [TM][16]
#pragma unroll
    for (int i = 0; i < 8; i++) {
        rval[(ty * 8 + i) * 16 + tx] = best[i];
        ridx[(ty * 8 + i) * 16 + tx] = bidx[i];
    }
    __syncthreads();
    if (tid < TM) {
        float b = rval[tid * 16 + 0];
        int bi = ridx[tid * 16 + 0];
#pragma unroll
        for (int t = 1; t < 16; t++) {
            float v = rval[tid * 16 + t];
            int vi = ridx[tid * 16 + t];
            if (v > b || (v == b && vi < bi)) { b = v; bi = vi; }
        }
        finalIdx[tid] = bi;
        if (write_idx)
            out[(size_t)N * DDIM + rowBase + tid] = (float)bi;
    }
    __syncthreads();

    // gather quantized rows (emb rows are L2-hot)
#pragma unroll
    for (int t = 0; t < (TM * DDIM / 4) / 256; t++) {
        int idx = tid + t * 256;
        int row = idx >> 4;
        int c4 = idx & 15;
        float4 v = reinterpret_cast<const float4*>(
            emb + (size_t)finalIdx[row] * DDIM)[c4];
        reinterpret_cast<float4*>(out + (size_t)(rowBase + row) * DDIM)[c4] = v;
    }
}

extern "C" void kernel_launch(void* const* d_in, const int* in_sizes, int n_in,
                              void* d_out, int out_size) {
    const float* z = (const float*)d_in[0];
    const float* emb = (const float*)d_in[1];
    if (n_in >= 2 && in_sizes[1] > in_sizes[0]) {
        const float* t = z; z = emb; emb = t;
    }
    int zsize = in_sizes[0], esize = in_sizes[1];
    if (esize > zsize) { int t = zsize; zsize = esize; esize = t; }

    int N = zsize / DDIM;   // 65536
    int K = esize / DDIM;   // 1024
    float* out = (float*)d_out;
    int write_idx = (out_size >= N * DDIM + N) ? 1 : 0;

    cnorm_kernel<<<(K + 255) / 256, 256>>>(emb, K);

    int smem_bytes = (TM * DDIM + TKC * EPITCH * 2 + TKC) * (int)sizeof(float)
                     + TM * (int)sizeof(int);   // ~50.4 KB
    static int attr_set = 0;
    if (!attr_set) {
        cudaFuncSetAttribute(vq_kernel, cudaFuncAttributeMaxDynamicSharedMemorySize,
                             smem_bytes);
        attr_set = 1;
    }
    vq_kernel<<<N / TM, 256, smem_bytes>>>(z, emb, out, N, K, write_idx);
}

// round 6
// speedup vs baseline: 1.2531x; 1.0683x over previous
#include <cuda_runtime.h>
#include <cuda_bf16.h>

// VQ codebook quantization — FFMA2 + 8x4 tiling + LDS.128 (2 kk per load).
//   s[n,k] = z[n]·e[k] - 0.5*||e[k]||^2 ; idx[n] = argmax_k s ; out = e[idx]
// N=65536, D=64, K=1024. Output: [N*D quantized][N indices-as-float].
//
// Tile: 128 rows x 64-code chunks, 256 threads, per-thread 8 rows x 4 codes.
// z smem natural [row][d]: mainloop z reads are broadcast LDS.128.
// e smem pitch 33 float4 (528 B/row): aligned float4 staging stores, and
// mainloop LDS.128 bank-group = (tx+kk2) mod 8 -> exactly 2 phases, no
// conflicts. Per 2 kk-steps: 12 LDS.128 + 64 FFMA2 -> crossbar demand ~60%
// of fma-pipe demand; FMA is the sole bottleneck.

#define DDIM 64
#define TM 128
#define TKC 64
#define EPITCH4 33    // float4 per padded e row
#define KMAX 4096

__device__ float g_cnorm[KMAX];

__global__ void cnorm_kernel(const float* __restrict__ emb, int K) {
    int k = blockIdx.x * blockDim.x + threadIdx.x;
    if (k < K) {
        const float4* e4 = reinterpret_cast<const float4*>(emb + (size_t)k * DDIM);
        float s = 0.f;
#pragma unroll
        for (int i = 0; i < DDIM / 4; i++) {
            float4 v = e4[i];
            s += v.x * v.x + v.y * v.y + v.z * v.z + v.w * v.w;
        }
        g_cnorm[k] = 0.5f * s;
    }
}

#define FMA2(acc, a, b) \
    asm("fma.rn.f32x2 %0, %1, %2, %0;" : "+l"(acc) : "l"(a), "l"(b))

__global__ __launch_bounds__(256, 2)
void vq_kernel(const float* __restrict__ z, const float* __restrict__ emb,
               float* __restrict__ out, int N, int K, int write_idx) {
    extern __shared__ float smem[];
    float* zs = smem;                               // TM*DDIM = 32 KB
    float* es = smem + TM * DDIM;                   // TKC*EPITCH4*4 floats (33 KB)
    float* cns = es + TKC * EPITCH4 * 4;            // TKC
    int* finalIdx = (int*)(cns + TKC);              // TM

    const int tid = threadIdx.x;
    const int tx = tid & 15;       // code groups: codes tx + 16*j
    const int ty = tid >> 4;       // row group: rows ty*8 .. ty*8+7
    const int rowBase = blockIdx.x * TM;

    // stage z tile, natural [row][d] (coalesced LDG.128 / STS.128)
#pragma unroll
    for (int t = 0; t < (TM * DDIM / 4) / 256; t++) {   // 8 iters
        int idx = tid + t * 256;
        int row = idx >> 4;
        int c4 = idx & 15;
        reinterpret_cast<float4*>(zs)[row * 16 + c4] =
            reinterpret_cast<const float4*>(z + (size_t)(rowBase + row) * DDIM)[c4];
    }

    float best[8];
    int bidx[8];
#pragma unroll
    for (int i = 0; i < 8; i++) { best[i] = -3.402823466e38f; bidx[i] = 0; }

    const ulonglong2* zs4 = reinterpret_cast<const ulonglong2*>(zs);
    const ulonglong2* es4 = reinterpret_cast<const ulonglong2*>(es);

    for (int kc = 0; kc < K; kc += TKC) {
        __syncthreads();
        // stage e chunk: 64 codes x 16 float4, pitch EPITCH4 (aligned stores)
        {
            const float4* src = reinterpret_cast<const float4*>(
                emb + (size_t)kc * DDIM);
            float4* dst = reinterpret_cast<float4*>(es);
#pragma unroll
            for (int t = 0; t < (TKC * DDIM / 4) / 256; t++) {  // 4 iters
                int idx = tid + t * 256;
                int code = idx >> 4;
                int c4 = idx & 15;
                dst[code * EPITCH4 + c4] = src[code * 16 + c4];
            }
        }
        if (tid < TKC) cns[tid] = g_cnorm[kc + tid];
        __syncthreads();

        unsigned long long acc[8][4];
#pragma unroll
        for (int i = 0; i < 8; i++)
#pragma unroll
            for (int j = 0; j < 4; j++) acc[i][j] = 0ull;

#pragma unroll
        for (int kk2 = 0; kk2 < DDIM / 4; kk2++) {   // 16 iters, 4 dims each
            ulonglong2 zz[8];
#pragma unroll
            for (int i = 0; i < 8; i++)
                zz[i] = zs4[(ty * 8 + i) * 16 + kk2];        // broadcast
            ulonglong2 ee[4];
#pragma unroll
            for (int j = 0; j < 4; j++)
                ee[j] = es4[(tx + 16 * j) * EPITCH4 + kk2];  // 2-phase, no conflict
#pragma unroll
            for (int i = 0; i < 8; i++)
#pragma unroll
                for (int j = 0; j < 4; j++) {
                    FMA2(acc[i][j], zz[i].x, ee[j].x);
                    FMA2(acc[i][j], zz[i].y, ee[j].y);
                }
        }

        // fold into running per-row argmax
#pragma unroll
        for (int j = 0; j < 4; j++) {
            int code = kc + tx + 16 * j;
            float cn = cns[tx + 16 * j];
#pragma unroll
            for (int i = 0; i < 8; i++) {
                float lo, hi;
                asm("mov.b64 {%0, %1}, %2;" : "=f"(lo), "=f"(hi) : "l"(acc[i][j]));
                float s = (lo + hi) - cn;
                if (s > best[i]) { best[i] = s; bidx[i] = code; }
            }
        }
    }

    __syncthreads();
    // cross-tx reduction (explicit index tie-break: tx-interleaved codes)
    float* rval = es;                       // [TM][16]
    int* ridx = (int*)(es + TM * 16);       // [TM][16]
#pragma unroll
    for (int i = 0; i < 8; i++) {
        rval[(ty * 8 + i) * 16 + tx] = best[i];
        ridx[(ty * 8 + i) * 16 + tx] = bidx[i];
    }
    __syncthreads();
    if (tid < TM) {
        float b = rval[tid * 16 + 0];
        int bi = ridx[tid * 16 + 0];
#pragma unroll
        for (int t = 1; t < 16; t++) {
            float v = rval[tid * 16 + t];
            int vi = ridx[tid * 16 + t];
            if (v > b || (v == b && vi < bi)) { b = v; bi = vi; }
        }
        finalIdx[tid] = bi;
        if (write_idx)
            out[(size_t)N * DDIM + rowBase + tid] = (float)bi;
    }
    __syncthreads();

    // gather quantized rows (emb rows are L2-hot)
#pragma unroll
    for (int t = 0; t < (TM * DDIM / 4) / 256; t++) {
        int idx = tid + t * 256;
        int row = idx >> 4;
        int c4 = idx & 15;
        float4 v = reinterpret_cast<const float4*>(
            emb + (size_t)finalIdx[row] * DDIM)[c4];
        reinterpret_cast<float4*>(out + (size_t)(rowBase + row) * DDIM)[c4] = v;
    }
}

extern "C" void kernel_launch(void* const* d_in, const int* in_sizes, int n_in,
                              void* d_out, int out_size) {
    const float* z = (const float*)d_in[0];
    const float* emb = (const float*)d_in[1];
    if (n_in >= 2 && in_sizes[1] > in_sizes[0]) {
        const float* t = z; z = emb; emb = t;
    }
    int zsize = in_sizes[0], esize = in_sizes[1];
    if (esize > zsize) { int t = zsize; zsize = esize; esize = t; }

    int N = zsize / DDIM;   // 65536
    int K = esize / DDIM;   // 1024
    float* out = (float*)d_out;
    int write_idx = (out_size >= N * DDIM + N) ? 1 : 0;

    cnorm_kernel<<<(K + 255) / 256, 256>>>(emb, K);

    int smem_bytes = (TM * DDIM + TKC * EPITCH4 * 4 + TKC) * (int)sizeof(float)
                     + TM * (int)sizeof(int);   // ~65.8 KB
    static int attr_set = 0;
    if (!attr_set) {
        cudaFuncSetAttribute(vq_kernel, cudaFuncAttributeMaxDynamicSharedMemorySize,
                             smem_bytes);
        attr_set = 1;
    }
    vq_kernel<<<N / TM, 256, smem_bytes>>>(z, emb, out, N, K, write_idx);
}

// round 7
// speedup vs baseline: 1.2645x; 1.0091x over previous
#include <cuda_runtime.h>
#include <cuda_bf16.h>

// VQ codebook quantization — FFMA2, 4x4 micro-tile, double-buffered operands.
//   s[n,k] = z[n]·e[k] - 0.5*||e[k]||^2 ; idx[n] = argmax_k s ; out = e[idx]
// N=65536, D=64, K=1024. Output: [N*D quantized][N indices-as-float].
//
// Block: 128 threads (tx 0..15 codes, ty 0..7 row-groups), tile 32 rows x
// 64-code chunks; per-thread 4 rows x 4 codes. z smem natural [row][d]
// (broadcast LDS.128); e smem pitch-33-float4 rows (aligned stores,
// min-phase reads). Mainloop ping-pongs operand registers: loads for step
// k+1 issue alongside FFMA2s of step k, hiding the 29cyc LDS latency that
// capped R6 at fma=49%.

#define DDIM 64
#define TM 32
#define TKC 64
#define EPITCH4 33    // float4 per padded e row
#define KMAX 4096

__device__ float g_cnorm[KMAX];

__global__ void cnorm_kernel(const float* __restrict__ emb, int K) {
    int k = blockIdx.x * blockDim.x + threadIdx.x;
    if (k < K) {
        const float4* e4 = reinterpret_cast<const float4*>(emb + (size_t)k * DDIM);
        float s = 0.f;
#pragma unroll
        for (int i = 0; i < DDIM / 4; i++) {
            float4 v = e4[i];
            s += v.x * v.x + v.y * v.y + v.z * v.z + v.w * v.w;
        }
        g_cnorm[k] = 0.5f * s;
    }
}

#define FMA2(acc, a, b) \
    asm("fma.rn.f32x2 %0, %1, %2, %0;" : "+l"(acc) : "l"(a), "l"(b))

__global__ __launch_bounds__(128, 4)
void vq_kernel(const float* __restrict__ z, const float* __restrict__ emb,
               float* __restrict__ out, int N, int K, int write_idx) {
    extern __shared__ float smem[];
    float* zs = smem;                               // TM*DDIM = 8 KB
    float* es = smem + TM * DDIM;                   // TKC*EPITCH4*4 floats (33 KB)
    float* cns = es + TKC * EPITCH4 * 4;            // TKC
    int* finalIdx = (int*)(cns + TKC);              // TM

    const int tid = threadIdx.x;
    const int tx = tid & 15;       // codes tx + 16*j, j=0..3
    const int ty = tid >> 4;       // rows ty*4 .. ty*4+3
    const int rowBase = blockIdx.x * TM;

    // stage z tile, natural [row][d]
#pragma unroll
    for (int t = 0; t < (TM * DDIM / 4) / 128; t++) {   // 4 iters
        int idx = tid + t * 128;
        int row = idx >> 4;
        int c4 = idx & 15;
        reinterpret_cast<float4*>(zs)[row * 16 + c4] =
            reinterpret_cast<const float4*>(z + (size_t)(rowBase + row) * DDIM)[c4];
    }

    float best[4];
    int bidx[4];
#pragma unroll
    for (int i = 0; i < 4; i++) { best[i] = -3.402823466e38f; bidx[i] = 0; }

    const ulonglong2* zs4 = reinterpret_cast<const ulonglong2*>(zs);
    const ulonglong2* es4 = reinterpret_cast<const ulonglong2*>(es);

    for (int kc = 0; kc < K; kc += TKC) {
        __syncthreads();
        // stage e chunk: 64 codes x 16 float4, pitch 33 (aligned)
        {
            const float4* src = reinterpret_cast<const float4*>(
                emb + (size_t)kc * DDIM);
            float4* dst = reinterpret_cast<float4*>(es);
#pragma unroll
            for (int t = 0; t < (TKC * DDIM / 4) / 128; t++) {  // 8 iters
                int idx = tid + t * 128;
                int code = idx >> 4;
                int c4 = idx & 15;
                dst[code * EPITCH4 + c4] = src[code * 16 + c4];
            }
        }
        if (tid < TKC) cns[tid] = g_cnorm[kc + tid];
        __syncthreads();

        unsigned long long acc[4][4];
#pragma unroll
        for (int i = 0; i < 4; i++)
#pragma unroll
            for (int j = 0; j < 4; j++) acc[i][j] = 0ull;

        // ---- double-buffered mainloop over 16 kk2 steps (4 dims each) ----
        ulonglong2 zzA[4], eeA[4], zzB[4], eeB[4];
#pragma unroll
        for (int i = 0; i < 4; i++) zzA[i] = zs4[(ty * 4 + i) * 16 + 0];
#pragma unroll
        for (int j = 0; j < 4; j++) eeA[j] = es4[(tx + 16 * j) * EPITCH4 + 0];

#pragma unroll
        for (int k2 = 0; k2 < 16; k2 += 2) {
            // prefetch k2+1 into B while consuming A
            if (k2 + 1 < 16) {
#pragma unroll
                for (int i = 0; i < 4; i++)
                    zzB[i] = zs4[(ty * 4 + i) * 16 + (k2 + 1)];
#pragma unroll
                for (int j = 0; j < 4; j++)
                    eeB[j] = es4[(tx + 16 * j) * EPITCH4 + (k2 + 1)];
            }
#pragma unroll
            for (int i = 0; i < 4; i++)
#pragma unroll
                for (int j = 0; j < 4; j++) {
                    FMA2(acc[i][j], zzA[i].x, eeA[j].x);
                    FMA2(acc[i][j], zzA[i].y, eeA[j].y);
                }
            // prefetch k2+2 into A while consuming B
            if (k2 + 2 < 16) {
#pragma unroll
                for (int i = 0; i < 4; i++)
                    zzA[i] = zs4[(ty * 4 + i) * 16 + (k2 + 2)];
#pragma unroll
                for (int j = 0; j < 4; j++)
                    eeA[j] = es4[(tx + 16 * j) * EPITCH4 + (k2 + 2)];
            }
#pragma unroll
            for (int i = 0; i < 4; i++)
#pragma unroll
                for (int j = 0; j < 4; j++) {
                    FMA2(acc[i][j], zzB[i].x, eeB[j].x);
                    FMA2(acc[i][j], zzB[i].y, eeB[j].y);
                }
        }

        // fold into running per-row argmax
#pragma unroll
        for (int j = 0; j < 4; j++) {
            int code = kc + tx + 16 * j;
            float cn = cns[tx + 16 * j];
#pragma unroll
            for (int i = 0; i < 4; i++) {
                float lo, hi;
                asm("mov.b64 {%0, %1}, %2;" : "=f"(lo), "=f"(hi) : "l"(acc[i][j]));
                float s = (lo + hi) - cn;
                if (s > best[i]) { best[i] = s; bidx[i] = code; }
            }
        }
    }

    __syncthreads();
    // cross-tx reduction (explicit index tie-break: tx-interleaved codes)
    float* rval = es;                       // [TM][16]
    int* ridx = (int*)(es + TM * 16);       // [TM][16]
#pragma unroll
    for (int i = 0; i < 4; i++) {
        rval[(ty * 4 + i) * 16 + tx] = best[i];
        ridx[(ty * 4 + i) * 16 + tx] = bidx[i];
    }
    __syncthreads();
    if (tid < TM) {
        float b = rval[tid * 16 + 0];
        int bi = ridx[tid * 16 + 0];
#pragma unroll
        for (int t = 1; t < 16; t++) {
            float v = rval[tid * 16 + t];
            int vi = ridx[tid * 16 + t];
            if (v > b || (v == b && vi < bi)) { b = v; bi = vi; }
        }
        finalIdx[tid] = bi;
        if (write_idx)
            out[(size_t)N * DDIM + rowBase + tid] = (float)bi;
    }
    __syncthreads();

    // gather quantized rows (emb rows are L2-hot)
#pragma unroll
    for (int t = 0; t < (TM * DDIM / 4) / 128; t++) {   // 4 iters
        int idx = tid + t * 128;
        int row = idx >> 4;
        int c4 = idx & 15;
        float4 v = reinterpret_cast<const float4*>(
            emb + (size_t)finalIdx[row] * DDIM)[c4];
        reinterpret_cast<float4*>(out + (size_t)(rowBase + row) * DDIM)[c4] = v;
    }
}

extern "C" void kernel_launch(void* const* d_in, const int* in_sizes, int n_in,
                              void* d_out, int out_size) {
    const float* z = (const float*)d_in[0];
    const float* emb = (const float*)d_in[1];
    if (n_in >= 2 && in_sizes[1] > in_sizes[0]) {
        const float* t = z; z = emb; emb = t;
    }
    int zsize = in_sizes[0], esize = in_sizes[1];
    if (esize > zsize) { int t = zsize; zsize = esize; esize = t; }

    int N = zsize / DDIM;   // 65536
    int K = esize / DDIM;   // 1024
    float* out = (float*)d_out;
    int write_idx = (out_size >= N * DDIM + N) ? 1 : 0;

    cnorm_kernel<<<(K + 255) / 256, 256>>>(emb, K);

    int smem_bytes = (TM * DDIM + TKC * EPITCH4 * 4 + TKC) * (int)sizeof(float)
                     + TM * (int)sizeof(int);   // ~41.5 KB
    static int attr_set = 0;
    if (!attr_set) {
        cudaFuncSetAttribute(vq_kernel, cudaFuncAttributeMaxDynamicSharedMemorySize,
                             smem_bytes);
        attr_set = 1;
    }
    vq_kernel<<<N / TM, 128, smem_bytes>>>(z, emb, out, N, K, write_idx);
}